// round 1
// baseline (speedup 1.0000x reference)
#include <cuda_runtime.h>
#include <math.h>

// Problem constants
#define Bn 2
#define Ln 1024
#define Dn 2048
#define Nn 16
#define Rn 128
#define En 160          // DT_RANK + 2*D_STATE
#define Mn (Bn*Ln)      // 2048 rows (b,l)
#define NCHUNK 16
#define LCH (Ln/NCHUNK) // 64 steps per chunk
#define SPLITK 8

// Scratch (no allocations allowed — device globals)
__device__ float g_u[Mn*Dn];                 // conv output u[b,l,d]
__device__ float g_part[SPLITK*Mn*En];       // gemm1 split-K partials
__device__ float g_xdbl[Mn*En];              // x_dbl = [dt | B | C]
__device__ float g_delta[Mn*Dn];             // softplus(dt @ W2^T + b2)
__device__ float g_Aneg[Dn*Nn];              // A = -exp(A_log)
__device__ float g_cA[Bn*NCHUNK*Nn*Dn];      // chunk prod(a)
__device__ float g_cB[Bn*NCHUNK*Nn*Dn];      // chunk composed b
__device__ float g_hin[Bn*NCHUNK*Nn*Dn];     // incoming h per chunk

// ---------------------------------------------------------------------------
// 1) Depthwise causal conv1d (k=4) + bias
// ---------------------------------------------------------------------------
__global__ void conv_kernel(const float* __restrict__ x,
                            const float* __restrict__ cw,
                            const float* __restrict__ cb) {
    int idx = blockIdx.x * 256 + threadIdx.x;   // = (b*L + l)*D + d
    int d = idx & (Dn - 1);
    int l = (idx >> 11) & (Ln - 1);
    const float* w = cw + d * 4;
    float acc = cb[d];
#pragma unroll
    for (int j = 0; j < 4; j++) {
        int ls = l - 3 + j;
        if (ls >= 0) acc += x[idx + (j - 3) * Dn] * w[j];
    }
    g_u[idx] = acc;
}

// ---------------------------------------------------------------------------
// 2) A = -exp(A_log)
// ---------------------------------------------------------------------------
__global__ void aprep_kernel(const float* __restrict__ alog) {
    int i = blockIdx.x * 256 + threadIdx.x;
    if (i < Dn * Nn) g_Aneg[i] = -expf(alog[i]);
}

// ---------------------------------------------------------------------------
// 3) GEMM1: partial[s][m][e] = sum_{k in split s} u[m][k] * W1[e][k]
//    BM=128, BN=160 (all of E), BK=16, split-K=8. 256 thr, 8x10 per thread.
// ---------------------------------------------------------------------------
__global__ void __launch_bounds__(256) gemm1_kernel(const float* __restrict__ W1) {
    __shared__ float As[16][129];
    __shared__ float Ws[16][161];
    int tid = threadIdx.x;
    int m0 = blockIdx.x * 128;
    int ks = blockIdx.y * (Dn / SPLITK);
    int tx = tid & 15, ty = tid >> 4;
    float acc[8][10];
#pragma unroll
    for (int i = 0; i < 8; i++)
#pragma unroll
        for (int j = 0; j < 10; j++) acc[i][j] = 0.f;

    for (int k0 = ks; k0 < ks + Dn / SPLITK; k0 += 16) {
#pragma unroll
        for (int i = 0; i < 8; i++) {
            int f = tid + i * 256; int m = f >> 4, k = f & 15;
            As[k][m] = g_u[(m0 + m) * Dn + k0 + k];
        }
#pragma unroll
        for (int i = 0; i < 10; i++) {
            int f = tid + i * 256; int e = f >> 4, k = f & 15;
            Ws[k][e] = W1[e * Dn + k0 + k];
        }
        __syncthreads();
#pragma unroll
        for (int k = 0; k < 16; k++) {
            float a[8], w[10];
#pragma unroll
            for (int i = 0; i < 8; i++) a[i] = As[k][ty * 8 + i];
#pragma unroll
            for (int j = 0; j < 10; j++) w[j] = Ws[k][tx + 16 * j];
#pragma unroll
            for (int i = 0; i < 8; i++)
#pragma unroll
                for (int j = 0; j < 10; j++) acc[i][j] += a[i] * w[j];
        }
        __syncthreads();
    }
    float* outp = g_part + (size_t)blockIdx.y * (Mn * En);
#pragma unroll
    for (int i = 0; i < 8; i++)
#pragma unroll
        for (int j = 0; j < 10; j++)
            outp[(m0 + ty * 8 + i) * En + tx + 16 * j] = acc[i][j];
}

// ---------------------------------------------------------------------------
// 4) Reduce split-K partials -> x_dbl
// ---------------------------------------------------------------------------
__global__ void reduce1_kernel() {
    int i = blockIdx.x * 256 + threadIdx.x;   // < Mn*En
    float s = 0.f;
#pragma unroll
    for (int p = 0; p < SPLITK; p++) s += g_part[(size_t)p * (Mn * En) + i];
    g_xdbl[i] = s;
}

// ---------------------------------------------------------------------------
// 5) GEMM2 + bias + softplus:
//    delta[m][d] = softplus(sum_r dt[m][r]*W2[d][r] + b2[d])
//    dt = x_dbl[:, 0:128] (ld = 160). BM=BN=128, BK=16, 8x8 per thread.
// ---------------------------------------------------------------------------
__global__ void __launch_bounds__(256) gemm2_kernel(const float* __restrict__ W2,
                                                    const float* __restrict__ b2) {
    __shared__ float As[16][129];
    __shared__ float Ws[16][129];
    int tid = threadIdx.x;
    int m0 = blockIdx.x * 128, n0 = blockIdx.y * 128;
    int tx = tid & 15, ty = tid >> 4;
    float acc[8][8];
#pragma unroll
    for (int i = 0; i < 8; i++)
#pragma unroll
        for (int j = 0; j < 8; j++) acc[i][j] = 0.f;

    for (int k0 = 0; k0 < Rn; k0 += 16) {
#pragma unroll
        for (int i = 0; i < 8; i++) {
            int f = tid + i * 256; int m = f >> 4, k = f & 15;
            As[k][m] = g_xdbl[(m0 + m) * En + k0 + k];
        }
#pragma unroll
        for (int i = 0; i < 8; i++) {
            int f = tid + i * 256; int n = f >> 4, k = f & 15;
            Ws[k][n] = W2[(n0 + n) * Rn + k0 + k];
        }
        __syncthreads();
#pragma unroll
        for (int k = 0; k < 16; k++) {
            float a[8], w[8];
#pragma unroll
            for (int i = 0; i < 8; i++) a[i] = As[k][ty * 8 + i];
#pragma unroll
            for (int j = 0; j < 8; j++) w[j] = Ws[k][tx + 16 * j];
#pragma unroll
            for (int i = 0; i < 8; i++)
#pragma unroll
                for (int j = 0; j < 8; j++) acc[i][j] += a[i] * w[j];
        }
        __syncthreads();
    }
#pragma unroll
    for (int i = 0; i < 8; i++) {
        int m = m0 + ty * 8 + i;
#pragma unroll
        for (int j = 0; j < 8; j++) {
            int n = n0 + tx + 16 * j;
            float v = acc[i][j] + b2[n];
            float sp = (v > 20.f) ? v : log1pf(__expf(v));
            g_delta[(size_t)m * Dn + n] = sp;
        }
    }
}

// ---------------------------------------------------------------------------
// 6) Scan pass 1: per (b,d,chunk) compute (prod a, composed b) over 64 steps
// ---------------------------------------------------------------------------
__global__ void __launch_bounds__(256) scan1_kernel() {
    __shared__ float Bsm[LCH][Nn];
    int tid = threadIdx.x;
    int d = blockIdx.x * 256 + tid;
    int c = blockIdx.y;
    int b = blockIdx.z;
    int lbase = b * Ln + c * LCH;
#pragma unroll
    for (int i = 0; i < (LCH * Nn) / 256; i++) {
        int f = tid + i * 256; int l = f >> 4, n = f & 15;
        Bsm[l][n] = g_xdbl[(lbase + l) * En + Rn + n];
    }
    __syncthreads();

    float A2[Nn];
#pragma unroll
    for (int n = 0; n < Nn; n++) A2[n] = g_Aneg[d * Nn + n];
    bool unif = true;
#pragma unroll
    for (int n = 1; n < Nn; n++) unif = unif && (A2[n] == A2[0]);

    float Ap[Nn], Bs[Nn];
#pragma unroll
    for (int n = 0; n < Nn; n++) { Ap[n] = 1.f; Bs[n] = 0.f; }

    const float* dptr = g_delta + (size_t)lbase * Dn + d;
    const float* uptr = g_u + (size_t)lbase * Dn + d;

    if (unif) {
        float a0 = A2[0];
        float ap = 1.f;
#pragma unroll 4
        for (int l = 0; l < LCH; l++) {
            float dl = dptr[(size_t)l * Dn];
            float uu = uptr[(size_t)l * Dn];
            float s = dl * uu;
            float dA = __expf(dl * a0);
            ap *= dA;
#pragma unroll
            for (int n = 0; n < Nn; n++) Bs[n] = dA * Bs[n] + s * Bsm[l][n];
        }
#pragma unroll
        for (int n = 0; n < Nn; n++) Ap[n] = ap;
    } else {
        for (int l = 0; l < LCH; l++) {
            float dl = dptr[(size_t)l * Dn];
            float uu = uptr[(size_t)l * Dn];
            float s = dl * uu;
#pragma unroll
            for (int n = 0; n < Nn; n++) {
                float dA = __expf(dl * A2[n]);
                Ap[n] *= dA;
                Bs[n] = dA * Bs[n] + s * Bsm[l][n];
            }
        }
    }
    size_t base = ((size_t)(b * NCHUNK + c) * Nn) * Dn + d;
#pragma unroll
    for (int n = 0; n < Nn; n++) {
        g_cA[base + (size_t)n * Dn] = Ap[n];
        g_cB[base + (size_t)n * Dn] = Bs[n];
    }
}

// ---------------------------------------------------------------------------
// 7) Inter-chunk scan: per (b,d,n) propagate h across 16 chunks
// ---------------------------------------------------------------------------
__global__ void scanmid_kernel() {
    int idx = blockIdx.x * 256 + threadIdx.x;  // b*(N*D) + n*D + d
    int d = idx & (Dn - 1);
    int n = (idx >> 11) & (Nn - 1);
    int b = idx >> 15;
    float h = 0.f;
    for (int c = 0; c < NCHUNK; c++) {
        size_t off = ((size_t)(b * NCHUNK + c) * Nn + n) * Dn + d;
        g_hin[off] = h;
        h = g_cA[off] * h + g_cB[off];
    }
}

// ---------------------------------------------------------------------------
// 8) Scan pass 2: replay with correct h_in, emit y
// ---------------------------------------------------------------------------
__global__ void __launch_bounds__(256) scan2_kernel(float* __restrict__ y,
                                                    const float* __restrict__ Dskip) {
    __shared__ float Bsm[LCH][Nn];
    __shared__ float Csm[LCH][Nn];
    int tid = threadIdx.x;
    int d = blockIdx.x * 256 + tid;
    int c = blockIdx.y;
    int b = blockIdx.z;
    int lbase = b * Ln + c * LCH;
#pragma unroll
    for (int i = 0; i < (LCH * Nn) / 256; i++) {
        int f = tid + i * 256; int l = f >> 4, n = f & 15;
        Bsm[l][n] = g_xdbl[(lbase + l) * En + Rn + n];
        Csm[l][n] = g_xdbl[(lbase + l) * En + Rn + Nn + n];
    }
    __syncthreads();

    float A2[Nn];
#pragma unroll
    for (int n = 0; n < Nn; n++) A2[n] = g_Aneg[d * Nn + n];
    bool unif = true;
#pragma unroll
    for (int n = 1; n < Nn; n++) unif = unif && (A2[n] == A2[0]);

    float h[Nn];
    size_t base = ((size_t)(b * NCHUNK + c) * Nn) * Dn + d;
#pragma unroll
    for (int n = 0; n < Nn; n++) h[n] = g_hin[base + (size_t)n * Dn];

    float dsk = Dskip[d];
    const float* dptr = g_delta + (size_t)lbase * Dn + d;
    const float* uptr = g_u + (size_t)lbase * Dn + d;
    float* yptr = y + (size_t)lbase * Dn + d;

    if (unif) {
        float a0 = A2[0];
#pragma unroll 4
        for (int l = 0; l < LCH; l++) {
            float dl = dptr[(size_t)l * Dn];
            float uu = uptr[(size_t)l * Dn];
            float s = dl * uu;
            float dA = __expf(dl * a0);
            float acc = 0.f;
#pragma unroll
            for (int n = 0; n < Nn; n++) {
                h[n] = dA * h[n] + s * Bsm[l][n];
                acc += h[n] * Csm[l][n];
            }
            yptr[(size_t)l * Dn] = acc + uu * dsk;
        }
    } else {
        for (int l = 0; l < LCH; l++) {
            float dl = dptr[(size_t)l * Dn];
            float uu = uptr[(size_t)l * Dn];
            float s = dl * uu;
            float acc = 0.f;
#pragma unroll
            for (int n = 0; n < Nn; n++) {
                float dA = __expf(dl * A2[n]);
                h[n] = dA * h[n] + s * Bsm[l][n];
                acc += h[n] * Csm[l][n];
            }
            yptr[(size_t)l * Dn] = acc + uu * dsk;
        }
    }
}

// ---------------------------------------------------------------------------
// Launch
// ---------------------------------------------------------------------------
extern "C" void kernel_launch(void* const* d_in, const int* in_sizes, int n_in,
                              void* d_out, int out_size) {
    const float* x     = (const float*)d_in[0];
    const float* cw    = (const float*)d_in[1];
    const float* cb    = (const float*)d_in[2];
    const float* W1    = (const float*)d_in[3];
    const float* W2    = (const float*)d_in[4];
    const float* b2    = (const float*)d_in[5];
    const float* alog  = (const float*)d_in[6];
    const float* dskip = (const float*)d_in[7];
    float* y = (float*)d_out;

    conv_kernel<<<(Mn * Dn) / 256, 256>>>(x, cw, cb);
    aprep_kernel<<<(Dn * Nn) / 256, 256>>>(alog);
    gemm1_kernel<<<dim3(Mn / 128, SPLITK), 256>>>(W1);
    reduce1_kernel<<<(Mn * En) / 256, 256>>>();
    gemm2_kernel<<<dim3(Mn / 128, Dn / 128), 256>>>(W2, b2);
    scan1_kernel<<<dim3(Dn / 256, NCHUNK, Bn), 256>>>();
    scanmid_kernel<<<(Bn * Nn * Dn) / 256, 256>>>();
    scan2_kernel<<<dim3(Dn / 256, NCHUNK, Bn), 256>>>(y, dskip);
}

// round 6
// speedup vs baseline: 1.4259x; 1.4259x over previous
#include <cuda_runtime.h>
#include <cuda_bf16.h>
#include <math.h>
#include <stdint.h>

// ---------------------------------------------------------------------------
// Problem constants
// ---------------------------------------------------------------------------
#define Bn 2
#define Ln 1024
#define Dn 2048
#define Nn 16
#define Rn 128
#define En 160          // DT_RANK + 2*D_STATE
#define Mn (Bn*Ln)      // 2048 rows (b,l)
#define NCHUNK 16
#define LCH (Ln/NCHUNK) // 64 steps per chunk
#define SPLITK 8

// ---------------------------------------------------------------------------
// Device scratch (no allocations allowed)
// ---------------------------------------------------------------------------
__device__ float          g_u[(size_t)Mn*Dn];        // conv output u[b,l,d] fp32
__device__ __nv_bfloat16  g_uhi[(size_t)Mn*Dn];      // u split-bf16 hi
__device__ __nv_bfloat16  g_ulo[(size_t)Mn*Dn];      // u split-bf16 lo
__device__ __nv_bfloat16  g_w1hi[En*Dn];             // xproj_w hi
__device__ __nv_bfloat16  g_w1lo[En*Dn];
__device__ __nv_bfloat16  g_w2hi[Dn*Rn];             // dtproj_w hi
__device__ __nv_bfloat16  g_w2lo[Dn*Rn];
__device__ __nv_bfloat16  g_dthi[Mn*Rn];             // dt (x_dbl[:, :128]) hi
__device__ __nv_bfloat16  g_dtlo[Mn*Rn];
__device__ float          g_part[SPLITK*Mn*En];      // gemm1 split-K partials
__device__ float          g_xdbl[Mn*En];             // x_dbl = [dt | B | C]
__device__ float          g_delta[(size_t)Mn*Dn];    // softplus(...)
__device__ float          g_Aneg[Dn*Nn];             // A = -exp(A_log)
__device__ float          g_cA[Bn*NCHUNK*Nn*Dn];     // chunk prod(a)
__device__ float          g_cB[Bn*NCHUNK*Nn*Dn];     // chunk composed b
__device__ float          g_hin[Bn*NCHUNK*Nn*Dn];    // incoming h per chunk

// ---------------------------------------------------------------------------
// Warp-MMA helpers (HMMA path — base sm_100 target has no tcgen05)
// ---------------------------------------------------------------------------
__device__ __forceinline__ uint32_t smem_u32(const void* p) {
    uint32_t a;
    asm("{ .reg .u64 t; cvta.to.shared.u64 t, %1; cvt.u32.u64 %0, t; }"
        : "=r"(a) : "l"(p));
    return a;
}

__device__ __forceinline__ void ldsm4(uint32_t* r, uint32_t addr) {
    asm volatile("ldmatrix.sync.aligned.m8n8.x4.shared.b16 {%0,%1,%2,%3}, [%4];"
                 : "=r"(r[0]), "=r"(r[1]), "=r"(r[2]), "=r"(r[3]) : "r"(addr));
}
__device__ __forceinline__ void ldsm2(uint32_t* r, uint32_t addr) {
    asm volatile("ldmatrix.sync.aligned.m8n8.x2.shared.b16 {%0,%1}, [%2];"
                 : "=r"(r[0]), "=r"(r[1]) : "r"(addr));
}
__device__ __forceinline__ void mma_bf16(float* c, const uint32_t* a, const uint32_t* b) {
    asm volatile(
        "mma.sync.aligned.m16n8k16.row.col.f32.bf16.bf16.f32 "
        "{%0,%1,%2,%3}, {%4,%5,%6,%7}, {%8,%9}, {%0,%1,%2,%3};"
        : "+f"(c[0]), "+f"(c[1]), "+f"(c[2]), "+f"(c[3])
        : "r"(a[0]), "r"(a[1]), "r"(a[2]), "r"(a[3]), "r"(b[0]), "r"(b[1]));
}

// ---------------------------------------------------------------------------
// 1) Depthwise causal conv1d (k=4) + bias; emit fp32 + split-bf16
// ---------------------------------------------------------------------------
__global__ void conv_kernel(const float* __restrict__ x,
                            const float* __restrict__ cw,
                            const float* __restrict__ cb) {
    int idx = blockIdx.x * 256 + threadIdx.x;   // = (b*L + l)*D + d
    int d = idx & (Dn - 1);
    int l = (idx >> 11) & (Ln - 1);
    const float* w = cw + d * 4;
    float acc = cb[d];
#pragma unroll
    for (int j = 0; j < 4; j++) {
        int ls = l - 3 + j;
        if (ls >= 0) acc += x[idx + (j - 3) * Dn] * w[j];
    }
    g_u[idx] = acc;
    __nv_bfloat16 h = __float2bfloat16(acc);
    g_uhi[idx] = h;
    g_ulo[idx] = __float2bfloat16(acc - __bfloat162float(h));
}

// ---------------------------------------------------------------------------
// 2) A = -exp(A_log)
// ---------------------------------------------------------------------------
__global__ void aprep_kernel(const float* __restrict__ alog) {
    int i = blockIdx.x * 256 + threadIdx.x;
    if (i < Dn * Nn) g_Aneg[i] = -expf(alog[i]);
}

// ---------------------------------------------------------------------------
// 2b) Weight split-bf16 conversion (W1: 160x2048, W2: 2048x128)
// ---------------------------------------------------------------------------
__global__ void wconv_kernel(const float* __restrict__ W1,
                             const float* __restrict__ W2) {
    int i = blockIdx.x * 256 + threadIdx.x;
    if (i < En * Dn) {
        float v = W1[i];
        __nv_bfloat16 h = __float2bfloat16(v);
        g_w1hi[i] = h;
        g_w1lo[i] = __float2bfloat16(v - __bfloat162float(h));
    }
    if (i < Dn * Rn) {
        float v = W2[i];
        __nv_bfloat16 h = __float2bfloat16(v);
        g_w2hi[i] = h;
        g_w2lo[i] = __float2bfloat16(v - __bfloat162float(h));
    }
}

// ---------------------------------------------------------------------------
// 3) GEMM1 (mma.sync bf16, split-bf16 3-product):
//    part[s][m][e] = sum_{k in split} u[m][k] * W1[e][k]
//    Block 128x160, 8 warps (2m x 4n), warp 64x40, BK=32. grid (16, 8).
// ---------------------------------------------------------------------------
#define PAD 40   // smem row stride in bf16 (80B): conflict-free ldmatrix

__global__ void __launch_bounds__(256, 1) gemm1_mma() {
    __shared__ __align__(16) __nv_bfloat16 sAhi[128 * PAD];
    __shared__ __align__(16) __nv_bfloat16 sAlo[128 * PAD];
    __shared__ __align__(16) __nv_bfloat16 sBhi[160 * PAD];
    __shared__ __align__(16) __nv_bfloat16 sBlo[160 * PAD];

    int tid = threadIdx.x;
    int lane = tid & 31, wid = tid >> 5;
    int wm = wid & 1, wn = wid >> 1;       // 2 x 4 warps
    int m0 = blockIdx.x * 128;
    int kbase = blockIdx.y * (Dn / SPLITK);

    float acc[4][5][4];
#pragma unroll
    for (int i = 0; i < 4; i++)
#pragma unroll
        for (int j = 0; j < 5; j++)
#pragma unroll
            for (int t = 0; t < 4; t++) acc[i][j][t] = 0.f;

    // precomputed ldmatrix lane addressing pieces
    int a_r = (lane & 7) + ((lane >> 3) & 1) * 8;   // A: row within 16
    int a_c = (lane >> 4) * 8;                      // A: k col within 16
    int b_r4 = (lane & 7) + (lane >> 4) * 8;        // B x4: n row within 16
    int b_c  = ((lane >> 3) & 1) * 8;               // B: k col within 16
    int b_r2 = lane & 7;                            // B x2: n row within 8

    for (int k0 = 0; k0 < Dn / SPLITK; k0 += 32) {
        // A tiles: 128 rows x 16 u32
#pragma unroll
        for (int i = 0; i < 8; i++) {
            int f = tid + i * 256; int row = f >> 4, kw = f & 15;
            size_t src = (size_t)(m0 + row) * Dn + kbase + k0 + kw * 2;
            *(uint32_t*)&sAhi[row * PAD + kw * 2] = *(const uint32_t*)(g_uhi + src);
            *(uint32_t*)&sAlo[row * PAD + kw * 2] = *(const uint32_t*)(g_ulo + src);
        }
        // B tiles: 160 rows x 16 u32
#pragma unroll
        for (int i = 0; i < 10; i++) {
            int f = tid + i * 256; int row = f >> 4, kw = f & 15;
            size_t src = (size_t)row * Dn + kbase + k0 + kw * 2;
            *(uint32_t*)&sBhi[row * PAD + kw * 2] = *(const uint32_t*)(g_w1hi + src);
            *(uint32_t*)&sBlo[row * PAD + kw * 2] = *(const uint32_t*)(g_w1lo + src);
        }
        __syncthreads();

#pragma unroll
        for (int kk = 0; kk < 32; kk += 16) {
            uint32_t ah[4][4], al[4][4], bh[5][2], bl[5][2];
#pragma unroll
            for (int mt = 0; mt < 4; mt++) {
                int off = (wm * 64 + mt * 16 + a_r) * PAD + kk + a_c;
                ldsm4(ah[mt], smem_u32(&sAhi[off]));
                ldsm4(al[mt], smem_u32(&sAlo[off]));
            }
#pragma unroll
            for (int g = 0; g < 2; g++) {
                int off = (wn * 40 + g * 16 + b_r4) * PAD + kk + b_c;
                uint32_t t[4];
                ldsm4(t, smem_u32(&sBhi[off]));
                bh[2 * g][0] = t[0]; bh[2 * g][1] = t[1];
                bh[2 * g + 1][0] = t[2]; bh[2 * g + 1][1] = t[3];
                ldsm4(t, smem_u32(&sBlo[off]));
                bl[2 * g][0] = t[0]; bl[2 * g][1] = t[1];
                bl[2 * g + 1][0] = t[2]; bl[2 * g + 1][1] = t[3];
            }
            {
                int off = (wn * 40 + 32 + b_r2) * PAD + kk + b_c;
                ldsm2(bh[4], smem_u32(&sBhi[off]));
                ldsm2(bl[4], smem_u32(&sBlo[off]));
            }
#pragma unroll
            for (int mt = 0; mt < 4; mt++)
#pragma unroll
                for (int nt = 0; nt < 5; nt++) {
                    mma_bf16(acc[mt][nt], ah[mt], bh[nt]);
                    mma_bf16(acc[mt][nt], ah[mt], bl[nt]);
                    mma_bf16(acc[mt][nt], al[mt], bh[nt]);
                }
        }
        __syncthreads();
    }

    // Epilogue -> split-K partials
    float* outp = g_part + (size_t)blockIdx.y * (Mn * En);
#pragma unroll
    for (int mt = 0; mt < 4; mt++) {
        int row = m0 + wm * 64 + mt * 16 + (lane >> 2);
#pragma unroll
        for (int nt = 0; nt < 5; nt++) {
            int col = wn * 40 + nt * 8 + (lane & 3) * 2;
            *(float2*)(outp + (size_t)row * En + col) =
                make_float2(acc[mt][nt][0], acc[mt][nt][1]);
            *(float2*)(outp + (size_t)(row + 8) * En + col) =
                make_float2(acc[mt][nt][2], acc[mt][nt][3]);
        }
    }
}

// ---------------------------------------------------------------------------
// 4) Reduce split-K partials -> x_dbl; emit dt split-bf16 for e<128
// ---------------------------------------------------------------------------
__global__ void reduce1_kernel() {
    int i = blockIdx.x * 256 + threadIdx.x;   // < Mn*En
    float s = 0.f;
#pragma unroll
    for (int p = 0; p < SPLITK; p++) s += g_part[(size_t)p * (Mn * En) + i];
    g_xdbl[i] = s;
    int m = i / En;
    int e = i - m * En;
    if (e < Rn) {
        __nv_bfloat16 h = __float2bfloat16(s);
        g_dthi[m * Rn + e] = h;
        g_dtlo[m * Rn + e] = __float2bfloat16(s - __bfloat162float(h));
    }
}

// ---------------------------------------------------------------------------
// 5) GEMM2 (mma.sync bf16, split-bf16) + bias + softplus:
//    delta[m][d] = softplus(sum_r dt[m][r]*W2[d][r] + b2[d])
//    Block 128x128, 8 warps (2m x 4n), warp 64x32, BK=32. grid (16, 16).
// ---------------------------------------------------------------------------
__global__ void __launch_bounds__(256, 1) gemm2_mma(const float* __restrict__ b2) {
    __shared__ __align__(16) __nv_bfloat16 sAhi[128 * PAD];
    __shared__ __align__(16) __nv_bfloat16 sAlo[128 * PAD];
    __shared__ __align__(16) __nv_bfloat16 sBhi[128 * PAD];
    __shared__ __align__(16) __nv_bfloat16 sBlo[128 * PAD];

    int tid = threadIdx.x;
    int lane = tid & 31, wid = tid >> 5;
    int wm = wid & 1, wn = wid >> 1;       // 2 x 4 warps
    int m0 = blockIdx.x * 128, n0 = blockIdx.y * 128;

    float acc[4][4][4];
#pragma unroll
    for (int i = 0; i < 4; i++)
#pragma unroll
        for (int j = 0; j < 4; j++)
#pragma unroll
            for (int t = 0; t < 4; t++) acc[i][j][t] = 0.f;

    int a_r = (lane & 7) + ((lane >> 3) & 1) * 8;
    int a_c = (lane >> 4) * 8;
    int b_r4 = (lane & 7) + (lane >> 4) * 8;
    int b_c  = ((lane >> 3) & 1) * 8;

    for (int k0 = 0; k0 < Rn; k0 += 32) {
#pragma unroll
        for (int i = 0; i < 8; i++) {
            int f = tid + i * 256; int row = f >> 4, kw = f & 15;
            size_t srcA = (size_t)(m0 + row) * Rn + k0 + kw * 2;
            size_t srcB = (size_t)(n0 + row) * Rn + k0 + kw * 2;
            *(uint32_t*)&sAhi[row * PAD + kw * 2] = *(const uint32_t*)(g_dthi + srcA);
            *(uint32_t*)&sAlo[row * PAD + kw * 2] = *(const uint32_t*)(g_dtlo + srcA);
            *(uint32_t*)&sBhi[row * PAD + kw * 2] = *(const uint32_t*)(g_w2hi + srcB);
            *(uint32_t*)&sBlo[row * PAD + kw * 2] = *(const uint32_t*)(g_w2lo + srcB);
        }
        __syncthreads();

#pragma unroll
        for (int kk = 0; kk < 32; kk += 16) {
            uint32_t ah[4][4], al[4][4], bh[4][2], bl[4][2];
#pragma unroll
            for (int mt = 0; mt < 4; mt++) {
                int off = (wm * 64 + mt * 16 + a_r) * PAD + kk + a_c;
                ldsm4(ah[mt], smem_u32(&sAhi[off]));
                ldsm4(al[mt], smem_u32(&sAlo[off]));
            }
#pragma unroll
            for (int g = 0; g < 2; g++) {
                int off = (wn * 32 + g * 16 + b_r4) * PAD + kk + b_c;
                uint32_t t[4];
                ldsm4(t, smem_u32(&sBhi[off]));
                bh[2 * g][0] = t[0]; bh[2 * g][1] = t[1];
                bh[2 * g + 1][0] = t[2]; bh[2 * g + 1][1] = t[3];
                ldsm4(t, smem_u32(&sBlo[off]));
                bl[2 * g][0] = t[0]; bl[2 * g][1] = t[1];
                bl[2 * g + 1][0] = t[2]; bl[2 * g + 1][1] = t[3];
            }
#pragma unroll
            for (int mt = 0; mt < 4; mt++)
#pragma unroll
                for (int nt = 0; nt < 4; nt++) {
                    mma_bf16(acc[mt][nt], ah[mt], bh[nt]);
                    mma_bf16(acc[mt][nt], ah[mt], bl[nt]);
                    mma_bf16(acc[mt][nt], al[mt], bh[nt]);
                }
        }
        __syncthreads();
    }

    // Epilogue: bias + softplus straight from registers
#pragma unroll
    for (int mt = 0; mt < 4; mt++) {
        int row = m0 + wm * 64 + mt * 16 + (lane >> 2);
#pragma unroll
        for (int nt = 0; nt < 4; nt++) {
            int col = n0 + wn * 32 + nt * 8 + (lane & 3) * 2;
            float bb0 = __ldg(b2 + col), bb1 = __ldg(b2 + col + 1);
            float t0 = acc[mt][nt][0] + bb0, t1 = acc[mt][nt][1] + bb1;
            float t2 = acc[mt][nt][2] + bb0, t3 = acc[mt][nt][3] + bb1;
            t0 = (t0 > 20.f) ? t0 : log1pf(__expf(t0));
            t1 = (t1 > 20.f) ? t1 : log1pf(__expf(t1));
            t2 = (t2 > 20.f) ? t2 : log1pf(__expf(t2));
            t3 = (t3 > 20.f) ? t3 : log1pf(__expf(t3));
            *(float2*)(g_delta + (size_t)row * Dn + col) = make_float2(t0, t1);
            *(float2*)(g_delta + (size_t)(row + 8) * Dn + col) = make_float2(t2, t3);
        }
    }
}

// ---------------------------------------------------------------------------
// 6) Scan pass 1: per (b,d,chunk) compute (prod a, composed b) over 64 steps
// ---------------------------------------------------------------------------
__global__ void __launch_bounds__(256) scan1_kernel() {
    __shared__ float Bsm[LCH][Nn];
    int tid = threadIdx.x;
    int d = blockIdx.x * 256 + tid;
    int c = blockIdx.y;
    int b = blockIdx.z;
    int lbase = b * Ln + c * LCH;
#pragma unroll
    for (int i = 0; i < (LCH * Nn) / 256; i++) {
        int f = tid + i * 256; int l = f >> 4, n = f & 15;
        Bsm[l][n] = g_xdbl[(lbase + l) * En + Rn + n];
    }
    __syncthreads();

    float A2[Nn];
#pragma unroll
    for (int n = 0; n < Nn; n++) A2[n] = g_Aneg[d * Nn + n];
    bool unif = true;
#pragma unroll
    for (int n = 1; n < Nn; n++) unif = unif && (A2[n] == A2[0]);

    float Ap[Nn], Bs[Nn];
#pragma unroll
    for (int n = 0; n < Nn; n++) { Ap[n] = 1.f; Bs[n] = 0.f; }

    const float* dptr = g_delta + (size_t)lbase * Dn + d;
    const float* uptr = g_u + (size_t)lbase * Dn + d;

    if (unif) {
        float a0 = A2[0];
        float ap = 1.f;
#pragma unroll 4
        for (int l = 0; l < LCH; l++) {
            float dl = dptr[(size_t)l * Dn];
            float uu = uptr[(size_t)l * Dn];
            float s = dl * uu;
            float dA = __expf(dl * a0);
            ap *= dA;
#pragma unroll
            for (int n = 0; n < Nn; n++) Bs[n] = dA * Bs[n] + s * Bsm[l][n];
        }
#pragma unroll
        for (int n = 0; n < Nn; n++) Ap[n] = ap;
    } else {
        for (int l = 0; l < LCH; l++) {
            float dl = dptr[(size_t)l * Dn];
            float uu = uptr[(size_t)l * Dn];
            float s = dl * uu;
#pragma unroll
            for (int n = 0; n < Nn; n++) {
                float dA = __expf(dl * A2[n]);
                Ap[n] *= dA;
                Bs[n] = dA * Bs[n] + s * Bsm[l][n];
            }
        }
    }
    size_t base = ((size_t)(b * NCHUNK + c) * Nn) * Dn + d;
#pragma unroll
    for (int n = 0; n < Nn; n++) {
        g_cA[base + (size_t)n * Dn] = Ap[n];
        g_cB[base + (size_t)n * Dn] = Bs[n];
    }
}

// ---------------------------------------------------------------------------
// 7) Inter-chunk scan: per (b,d,n) propagate h across 16 chunks
// ---------------------------------------------------------------------------
__global__ void scanmid_kernel() {
    int idx = blockIdx.x * 256 + threadIdx.x;  // b*(N*D) + n*D + d
    int d = idx & (Dn - 1);
    int n = (idx >> 11) & (Nn - 1);
    int b = idx >> 15;
    float h = 0.f;
    for (int c = 0; c < NCHUNK; c++) {
        size_t off = ((size_t)(b * NCHUNK + c) * Nn + n) * Dn + d;
        g_hin[off] = h;
        h = g_cA[off] * h + g_cB[off];
    }
}

// ---------------------------------------------------------------------------
// 8) Scan pass 2: replay with correct h_in, emit y
// ---------------------------------------------------------------------------
__global__ void __launch_bounds__(256) scan2_kernel(float* __restrict__ y,
                                                    const float* __restrict__ Dskip) {
    __shared__ float Bsm[LCH][Nn];
    __shared__ float Csm[LCH][Nn];
    int tid = threadIdx.x;
    int d = blockIdx.x * 256 + tid;
    int c = blockIdx.y;
    int b = blockIdx.z;
    int lbase = b * Ln + c * LCH;
#pragma unroll
    for (int i = 0; i < (LCH * Nn) / 256; i++) {
        int f = tid + i * 256; int l = f >> 4, n = f & 15;
        Bsm[l][n] = g_xdbl[(lbase + l) * En + Rn + n];
        Csm[l][n] = g_xdbl[(lbase + l) * En + Rn + Nn + n];
    }
    __syncthreads();

    float A2[Nn];
#pragma unroll
    for (int n = 0; n < Nn; n++) A2[n] = g_Aneg[d * Nn + n];
    bool unif = true;
#pragma unroll
    for (int n = 1; n < Nn; n++) unif = unif && (A2[n] == A2[0]);

    float h[Nn];
    size_t base = ((size_t)(b * NCHUNK + c) * Nn) * Dn + d;
#pragma unroll
    for (int n = 0; n < Nn; n++) h[n] = g_hin[base + (size_t)n * Dn];

    float dsk = Dskip[d];
    const float* dptr = g_delta + (size_t)lbase * Dn + d;
    const float* uptr = g_u + (size_t)lbase * Dn + d;
    float* yptr = y + (size_t)lbase * Dn + d;

    if (unif) {
        float a0 = A2[0];
#pragma unroll 4
        for (int l = 0; l < LCH; l++) {
            float dl = dptr[(size_t)l * Dn];
            float uu = uptr[(size_t)l * Dn];
            float s = dl * uu;
            float dA = __expf(dl * a0);
            float acc = 0.f;
#pragma unroll
            for (int n = 0; n < Nn; n++) {
                h[n] = dA * h[n] + s * Bsm[l][n];
                acc += h[n] * Csm[l][n];
            }
            yptr[(size_t)l * Dn] = acc + uu * dsk;
        }
    } else {
        for (int l = 0; l < LCH; l++) {
            float dl = dptr[(size_t)l * Dn];
            float uu = uptr[(size_t)l * Dn];
            float s = dl * uu;
            float acc = 0.f;
#pragma unroll
            for (int n = 0; n < Nn; n++) {
                float dA = __expf(dl * A2[n]);
                h[n] = dA * h[n] + s * Bsm[l][n];
                acc += h[n] * Csm[l][n];
            }
            yptr[(size_t)l * Dn] = acc + uu * dsk;
        }
    }
}

// ---------------------------------------------------------------------------
// Launch
// ---------------------------------------------------------------------------
extern "C" void kernel_launch(void* const* d_in, const int* in_sizes, int n_in,
                              void* d_out, int out_size) {
    const float* x     = (const float*)d_in[0];
    const float* cw    = (const float*)d_in[1];
    const float* cb    = (const float*)d_in[2];
    const float* W1    = (const float*)d_in[3];
    const float* W2    = (const float*)d_in[4];
    const float* b2    = (const float*)d_in[5];
    const float* alog  = (const float*)d_in[6];
    const float* dskip = (const float*)d_in[7];
    float* y = (float*)d_out;

    conv_kernel<<<(Mn * Dn) / 256, 256>>>(x, cw, cb);
    aprep_kernel<<<(Dn * Nn) / 256, 256>>>(alog);
    wconv_kernel<<<(En * Dn) / 256, 256>>>(W1, W2);
    gemm1_mma<<<dim3(Mn / 128, SPLITK), 256>>>();
    reduce1_kernel<<<(Mn * En) / 256, 256>>>();
    gemm2_mma<<<dim3(Mn / 128, Dn / 128), 256>>>(b2);
    scan1_kernel<<<dim3(Dn / 256, NCHUNK, Bn), 256>>>();
    scanmid_kernel<<<(Bn * Nn * Dn) / 256, 256>>>();
    scan2_kernel<<<dim3(Dn / 256, NCHUNK, Bn), 256>>>(y, dskip);
}

// round 7
// speedup vs baseline: 1.4746x; 1.0342x over previous
#include <cuda_runtime.h>
#include <cuda_bf16.h>
#include <math.h>
#include <stdint.h>

// ---------------------------------------------------------------------------
// Problem constants
// ---------------------------------------------------------------------------
#define Bn 2
#define Ln 1024
#define Dn 2048
#define Nn 16
#define Rn 128
#define En 160          // DT_RANK + 2*D_STATE
#define Mn (Bn*Ln)      // 2048 rows (b,l)
#define NCHUNK 16
#define LCH (Ln/NCHUNK) // 64 steps per chunk
#define SPLITK 8

// ---------------------------------------------------------------------------
// Device scratch (no allocations allowed)
// ---------------------------------------------------------------------------
__device__ float          g_u[(size_t)Mn*Dn];        // conv output u[b,l,d] fp32
__device__ __nv_bfloat16  g_uhi[(size_t)Mn*Dn];      // u split-bf16 hi
__device__ __nv_bfloat16  g_ulo[(size_t)Mn*Dn];      // u split-bf16 lo
__device__ __nv_bfloat16  g_w1hi[En*Dn];             // xproj_w hi
__device__ __nv_bfloat16  g_w1lo[En*Dn];
__device__ __nv_bfloat16  g_w2hi[Dn*Rn];             // dtproj_w hi
__device__ __nv_bfloat16  g_w2lo[Dn*Rn];
__device__ __nv_bfloat16  g_dthi[Mn*Rn];             // dt (x_dbl[:, :128]) hi
__device__ __nv_bfloat16  g_dtlo[Mn*Rn];
__device__ float          g_part[SPLITK*Mn*En];      // gemm1 split-K partials
__device__ float          g_xdbl[Mn*En];             // x_dbl = [dt | B | C]
__device__ float          g_delta[(size_t)Mn*Dn];    // softplus(...)
__device__ float          g_Aneg[Dn*Nn];             // A = -exp(A_log)
__device__ float          g_cA[Bn*NCHUNK*Nn*Dn];     // chunk prod(a)
__device__ float          g_cB[Bn*NCHUNK*Nn*Dn];     // chunk composed b
__device__ float          g_hin[Bn*NCHUNK*Nn*Dn];    // incoming h per chunk

// ---------------------------------------------------------------------------
// Warp-MMA + cp.async helpers (base sm_100 target: HMMA + LDGSTS)
// ---------------------------------------------------------------------------
__device__ __forceinline__ uint32_t smem_u32(const void* p) {
    uint32_t a;
    asm("{ .reg .u64 t; cvta.to.shared.u64 t, %1; cvt.u32.u64 %0, t; }"
        : "=r"(a) : "l"(p));
    return a;
}
__device__ __forceinline__ void cp16(uint32_t dst, const void* src) {
    asm volatile("cp.async.cg.shared.global [%0], [%1], 16;"
                 :: "r"(dst), "l"(src));
}
#define CP_COMMIT() asm volatile("cp.async.commit_group;" ::: "memory")
#define CP_WAIT0()  asm volatile("cp.async.wait_group 0;" ::: "memory")

__device__ __forceinline__ void ldsm4(uint32_t* r, uint32_t addr) {
    asm volatile("ldmatrix.sync.aligned.m8n8.x4.shared.b16 {%0,%1,%2,%3}, [%4];"
                 : "=r"(r[0]), "=r"(r[1]), "=r"(r[2]), "=r"(r[3]) : "r"(addr));
}
__device__ __forceinline__ void ldsm2(uint32_t* r, uint32_t addr) {
    asm volatile("ldmatrix.sync.aligned.m8n8.x2.shared.b16 {%0,%1}, [%2];"
                 : "=r"(r[0]), "=r"(r[1]) : "r"(addr));
}
__device__ __forceinline__ void mma_bf16(float* c, const uint32_t* a, const uint32_t* b) {
    asm volatile(
        "mma.sync.aligned.m16n8k16.row.col.f32.bf16.bf16.f32 "
        "{%0,%1,%2,%3}, {%4,%5,%6,%7}, {%8,%9}, {%0,%1,%2,%3};"
        : "+f"(c[0]), "+f"(c[1]), "+f"(c[2]), "+f"(c[3])
        : "r"(a[0]), "r"(a[1]), "r"(a[2]), "r"(a[3]), "r"(b[0]), "r"(b[1]));
}

// ---------------------------------------------------------------------------
// 1) Depthwise causal conv1d (k=4) + bias; emit fp32 + split-bf16
// ---------------------------------------------------------------------------
__global__ void conv_kernel(const float* __restrict__ x,
                            const float* __restrict__ cw,
                            const float* __restrict__ cb) {
    int idx = blockIdx.x * 256 + threadIdx.x;   // = (b*L + l)*D + d
    int d = idx & (Dn - 1);
    int l = (idx >> 11) & (Ln - 1);
    const float* w = cw + d * 4;
    float acc = cb[d];
#pragma unroll
    for (int j = 0; j < 4; j++) {
        int ls = l - 3 + j;
        if (ls >= 0) acc += x[idx + (j - 3) * Dn] * w[j];
    }
    g_u[idx] = acc;
    __nv_bfloat16 h = __float2bfloat16(acc);
    g_uhi[idx] = h;
    g_ulo[idx] = __float2bfloat16(acc - __bfloat162float(h));
}

// ---------------------------------------------------------------------------
// 2) A = -exp(A_log)
// ---------------------------------------------------------------------------
__global__ void aprep_kernel(const float* __restrict__ alog) {
    int i = blockIdx.x * 256 + threadIdx.x;
    if (i < Dn * Nn) g_Aneg[i] = -expf(alog[i]);
}

// ---------------------------------------------------------------------------
// 2b) Weight split-bf16 conversion (W1: 160x2048, W2: 2048x128)
// ---------------------------------------------------------------------------
__global__ void wconv_kernel(const float* __restrict__ W1,
                             const float* __restrict__ W2) {
    int i = blockIdx.x * 256 + threadIdx.x;
    if (i < En * Dn) {
        float v = W1[i];
        __nv_bfloat16 h = __float2bfloat16(v);
        g_w1hi[i] = h;
        g_w1lo[i] = __float2bfloat16(v - __bfloat162float(h));
    }
    if (i < Dn * Rn) {
        float v = W2[i];
        __nv_bfloat16 h = __float2bfloat16(v);
        g_w2hi[i] = h;
        g_w2lo[i] = __float2bfloat16(v - __bfloat162float(h));
    }
}

// ---------------------------------------------------------------------------
// 3) GEMM1 (mma.sync, split-bf16, 2-stage cp.async pipeline):
//    part[s][m][e] = sum_{k in split} u[m][k] * W1[e][k]
//    Block 128x160, 8 warps (2m x 4n), BK=32, 8 k-blocks. grid (16, 8).
// ---------------------------------------------------------------------------
#define PAD 40            // smem row stride in bf16 (80 B): conflict-free
// per-stage byte offsets within dynamic smem
#define G1_AHI 0
#define G1_ALO 10240
#define G1_BHI 20480
#define G1_BLO 33280
#define G1_STAGE 46080
#define G1_SMEM (2 * G1_STAGE)

__global__ void __launch_bounds__(256, 1) gemm1_mma() {
    extern __shared__ char smem[];
    uint32_t sb = smem_u32(smem);
    int tid = threadIdx.x;
    int lane = tid & 31, wid = tid >> 5;
    int wm = wid & 1, wn = wid >> 1;       // 2 x 4 warps
    int m0 = blockIdx.x * 128;
    int kbase = blockIdx.y * (Dn / SPLITK);

    float acc[4][5][4];
#pragma unroll
    for (int i = 0; i < 4; i++)
#pragma unroll
        for (int j = 0; j < 5; j++)
#pragma unroll
            for (int t = 0; t < 4; t++) acc[i][j][t] = 0.f;

    int a_r = (lane & 7) + ((lane >> 3) & 1) * 8;
    int a_c = (lane >> 4) * 8;
    int b_r4 = (lane & 7) + (lane >> 4) * 8;
    int b_c  = ((lane >> 3) & 1) * 8;
    int b_r2 = lane & 7;

    // ---- async stage loader ----
    auto load_stage = [&](int st, int kcol) {
        uint32_t sbase = sb + st * G1_STAGE;
#pragma unroll
        for (int i = 0; i < 2; i++) {                 // A: 512 chunks
            int cidx = tid + i * 256;
            int row = cidx >> 2, c16 = cidx & 3;
            uint32_t so = sbase + row * 80 + c16 * 16;
            size_t g = (size_t)(m0 + row) * Dn + kcol + c16 * 8;
            cp16(so + G1_AHI, g_uhi + g);
            cp16(so + G1_ALO, g_ulo + g);
        }
#pragma unroll
        for (int i = 0; i < 3; i++) {                 // B: 640 chunks
            int cidx = tid + i * 256;
            if (cidx < 640) {
                int row = cidx >> 2, c16 = cidx & 3;
                uint32_t so = sbase + row * 80 + c16 * 16;
                size_t g = (size_t)row * Dn + kcol + c16 * 8;
                cp16(so + G1_BHI, g_w1hi + g);
                cp16(so + G1_BLO, g_w1lo + g);
            }
        }
        CP_COMMIT();
    };

    load_stage(0, kbase);
    for (int kb = 0; kb < 8; kb++) {
        CP_WAIT0();
        __syncthreads();
        if (kb + 1 < 8) load_stage((kb + 1) & 1, kbase + (kb + 1) * 32);

        uint32_t sbase = sb + (kb & 1) * G1_STAGE;
#pragma unroll
        for (int kk = 0; kk < 32; kk += 16) {
            uint32_t ah[4][4], al[4][4], bh[5][2], bl[5][2];
#pragma unroll
            for (int mt = 0; mt < 4; mt++) {
                uint32_t a = sbase + G1_AHI +
                    (uint32_t)(((wm * 64 + mt * 16 + a_r) * PAD + kk + a_c) * 2);
                ldsm4(ah[mt], a);
                ldsm4(al[mt], a + (G1_ALO - G1_AHI));
            }
#pragma unroll
            for (int g = 0; g < 2; g++) {
                uint32_t a = sbase + G1_BHI +
                    (uint32_t)(((wn * 40 + g * 16 + b_r4) * PAD + kk + b_c) * 2);
                uint32_t t[4];
                ldsm4(t, a);
                bh[2 * g][0] = t[0]; bh[2 * g][1] = t[1];
                bh[2 * g + 1][0] = t[2]; bh[2 * g + 1][1] = t[3];
                ldsm4(t, a + (G1_BLO - G1_BHI));
                bl[2 * g][0] = t[0]; bl[2 * g][1] = t[1];
                bl[2 * g + 1][0] = t[2]; bl[2 * g + 1][1] = t[3];
            }
            {
                uint32_t a = sbase + G1_BHI +
                    (uint32_t)(((wn * 40 + 32 + b_r2) * PAD + kk + b_c) * 2);
                ldsm2(bh[4], a);
                ldsm2(bl[4], a + (G1_BLO - G1_BHI));
            }
#pragma unroll
            for (int mt = 0; mt < 4; mt++)
#pragma unroll
                for (int nt = 0; nt < 5; nt++) {
                    mma_bf16(acc[mt][nt], ah[mt], bh[nt]);
                    mma_bf16(acc[mt][nt], ah[mt], bl[nt]);
                    mma_bf16(acc[mt][nt], al[mt], bh[nt]);
                }
        }
    }

    // Epilogue -> split-K partials
    float* outp = g_part + (size_t)blockIdx.y * (Mn * En);
#pragma unroll
    for (int mt = 0; mt < 4; mt++) {
        int row = m0 + wm * 64 + mt * 16 + (lane >> 2);
#pragma unroll
        for (int nt = 0; nt < 5; nt++) {
            int col = wn * 40 + nt * 8 + (lane & 3) * 2;
            *(float2*)(outp + (size_t)row * En + col) =
                make_float2(acc[mt][nt][0], acc[mt][nt][1]);
            *(float2*)(outp + (size_t)(row + 8) * En + col) =
                make_float2(acc[mt][nt][2], acc[mt][nt][3]);
        }
    }
}

// ---------------------------------------------------------------------------
// 4) Reduce split-K partials -> x_dbl; emit dt split-bf16 for e<128
// ---------------------------------------------------------------------------
__global__ void reduce1_kernel() {
    int i = blockIdx.x * 256 + threadIdx.x;   // < Mn*En
    float s = 0.f;
#pragma unroll
    for (int p = 0; p < SPLITK; p++) s += g_part[(size_t)p * (Mn * En) + i];
    g_xdbl[i] = s;
    int m = i / En;
    int e = i - m * En;
    if (e < Rn) {
        __nv_bfloat16 h = __float2bfloat16(s);
        g_dthi[m * Rn + e] = h;
        g_dtlo[m * Rn + e] = __float2bfloat16(s - __bfloat162float(h));
    }
}

// ---------------------------------------------------------------------------
// 5) GEMM2 (mma.sync, split-bf16, 2-stage cp.async) + bias + softplus:
//    delta[m][d] = softplus(sum_r dt[m][r]*W2[d][r] + b2[d])
//    Block 128x128, 8 warps (2m x 4n), BK=32, 4 k-blocks. grid (16, 16).
// ---------------------------------------------------------------------------
#define G2_AHI 0
#define G2_ALO 10240
#define G2_BHI 20480
#define G2_BLO 30720
#define G2_STAGE 40960
#define G2_SMEM (2 * G2_STAGE)

__global__ void __launch_bounds__(256, 1) gemm2_mma(const float* __restrict__ b2) {
    extern __shared__ char smem[];
    uint32_t sb = smem_u32(smem);
    int tid = threadIdx.x;
    int lane = tid & 31, wid = tid >> 5;
    int wm = wid & 1, wn = wid >> 1;       // 2 x 4 warps
    int m0 = blockIdx.x * 128, n0 = blockIdx.y * 128;

    float acc[4][4][4];
#pragma unroll
    for (int i = 0; i < 4; i++)
#pragma unroll
        for (int j = 0; j < 4; j++)
#pragma unroll
            for (int t = 0; t < 4; t++) acc[i][j][t] = 0.f;

    int a_r = (lane & 7) + ((lane >> 3) & 1) * 8;
    int a_c = (lane >> 4) * 8;
    int b_r4 = (lane & 7) + (lane >> 4) * 8;
    int b_c  = ((lane >> 3) & 1) * 8;

    auto load_stage = [&](int st, int kcol) {
        uint32_t sbase = sb + st * G2_STAGE;
#pragma unroll
        for (int i = 0; i < 2; i++) {                 // A & B: 512 chunks each
            int cidx = tid + i * 256;
            int row = cidx >> 2, c16 = cidx & 3;
            uint32_t so = sbase + row * 80 + c16 * 16;
            size_t ga = (size_t)(m0 + row) * Rn + kcol + c16 * 8;
            size_t gb = (size_t)(n0 + row) * Rn + kcol + c16 * 8;
            cp16(so + G2_AHI, g_dthi + ga);
            cp16(so + G2_ALO, g_dtlo + ga);
            cp16(so + G2_BHI, g_w2hi + gb);
            cp16(so + G2_BLO, g_w2lo + gb);
        }
        CP_COMMIT();
    };

    load_stage(0, 0);
    for (int kb = 0; kb < 4; kb++) {
        CP_WAIT0();
        __syncthreads();
        if (kb + 1 < 4) load_stage((kb + 1) & 1, (kb + 1) * 32);

        uint32_t sbase = sb + (kb & 1) * G2_STAGE;
#pragma unroll
        for (int kk = 0; kk < 32; kk += 16) {
            uint32_t ah[4][4], al[4][4], bh[4][2], bl[4][2];
#pragma unroll
            for (int mt = 0; mt < 4; mt++) {
                uint32_t a = sbase + G2_AHI +
                    (uint32_t)(((wm * 64 + mt * 16 + a_r) * PAD + kk + a_c) * 2);
                ldsm4(ah[mt], a);
                ldsm4(al[mt], a + (G2_ALO - G2_AHI));
            }
#pragma unroll
            for (int g = 0; g < 2; g++) {
                uint32_t a = sbase + G2_BHI +
                    (uint32_t)(((wn * 32 + g * 16 + b_r4) * PAD + kk + b_c) * 2);
                uint32_t t[4];
                ldsm4(t, a);
                bh[2 * g][0] = t[0]; bh[2 * g][1] = t[1];
                bh[2 * g + 1][0] = t[2]; bh[2 * g + 1][1] = t[3];
                ldsm4(t, a + (G2_BLO - G2_BHI));
                bl[2 * g][0] = t[0]; bl[2 * g][1] = t[1];
                bl[2 * g + 1][0] = t[2]; bl[2 * g + 1][1] = t[3];
            }
#pragma unroll
            for (int mt = 0; mt < 4; mt++)
#pragma unroll
                for (int nt = 0; nt < 4; nt++) {
                    mma_bf16(acc[mt][nt], ah[mt], bh[nt]);
                    mma_bf16(acc[mt][nt], ah[mt], bl[nt]);
                    mma_bf16(acc[mt][nt], al[mt], bh[nt]);
                }
        }
    }

    // Epilogue: bias + softplus straight from registers
#pragma unroll
    for (int mt = 0; mt < 4; mt++) {
        int row = m0 + wm * 64 + mt * 16 + (lane >> 2);
#pragma unroll
        for (int nt = 0; nt < 4; nt++) {
            int col = n0 + wn * 32 + nt * 8 + (lane & 3) * 2;
            float bb0 = __ldg(b2 + col), bb1 = __ldg(b2 + col + 1);
            float t0 = acc[mt][nt][0] + bb0, t1 = acc[mt][nt][1] + bb1;
            float t2 = acc[mt][nt][2] + bb0, t3 = acc[mt][nt][3] + bb1;
            t0 = (t0 > 20.f) ? t0 : log1pf(__expf(t0));
            t1 = (t1 > 20.f) ? t1 : log1pf(__expf(t1));
            t2 = (t2 > 20.f) ? t2 : log1pf(__expf(t2));
            t3 = (t3 > 20.f) ? t3 : log1pf(__expf(t3));
            *(float2*)(g_delta + (size_t)row * Dn + col) = make_float2(t0, t1);
            *(float2*)(g_delta + (size_t)(row + 8) * Dn + col) = make_float2(t2, t3);
        }
    }
}

// ---------------------------------------------------------------------------
// 6) Scan pass 1: per (b,d,chunk) compute (prod a, composed b) over 64 steps
// ---------------------------------------------------------------------------
__global__ void __launch_bounds__(256) scan1_kernel() {
    __shared__ float Bsm[LCH][Nn];
    int tid = threadIdx.x;
    int d = blockIdx.x * 256 + tid;
    int c = blockIdx.y;
    int b = blockIdx.z;
    int lbase = b * Ln + c * LCH;
#pragma unroll
    for (int i = 0; i < (LCH * Nn) / 256; i++) {
        int f = tid + i * 256; int l = f >> 4, n = f & 15;
        Bsm[l][n] = g_xdbl[(lbase + l) * En + Rn + n];
    }
    __syncthreads();

    float A2[Nn];
#pragma unroll
    for (int n = 0; n < Nn; n++) A2[n] = g_Aneg[d * Nn + n];
    bool unif = true;
#pragma unroll
    for (int n = 1; n < Nn; n++) unif = unif && (A2[n] == A2[0]);

    float Ap[Nn], Bs[Nn];
#pragma unroll
    for (int n = 0; n < Nn; n++) { Ap[n] = 1.f; Bs[n] = 0.f; }

    const float* dptr = g_delta + (size_t)lbase * Dn + d;
    const float* uptr = g_u + (size_t)lbase * Dn + d;

    if (unif) {
        float a0 = A2[0];
        float ap = 1.f;
#pragma unroll 4
        for (int l = 0; l < LCH; l++) {
            float dl = dptr[(size_t)l * Dn];
            float uu = uptr[(size_t)l * Dn];
            float s = dl * uu;
            float dA = __expf(dl * a0);
            ap *= dA;
#pragma unroll
            for (int n = 0; n < Nn; n++) Bs[n] = dA * Bs[n] + s * Bsm[l][n];
        }
#pragma unroll
        for (int n = 0; n < Nn; n++) Ap[n] = ap;
    } else {
        for (int l = 0; l < LCH; l++) {
            float dl = dptr[(size_t)l * Dn];
            float uu = uptr[(size_t)l * Dn];
            float s = dl * uu;
#pragma unroll
            for (int n = 0; n < Nn; n++) {
                float dA = __expf(dl * A2[n]);
                Ap[n] *= dA;
                Bs[n] = dA * Bs[n] + s * Bsm[l][n];
            }
        }
    }
    size_t base = ((size_t)(b * NCHUNK + c) * Nn) * Dn + d;
#pragma unroll
    for (int n = 0; n < Nn; n++) {
        g_cA[base + (size_t)n * Dn] = Ap[n];
        g_cB[base + (size_t)n * Dn] = Bs[n];
    }
}

// ---------------------------------------------------------------------------
// 7) Inter-chunk scan: per (b,d,n) propagate h across 16 chunks
// ---------------------------------------------------------------------------
__global__ void scanmid_kernel() {
    int idx = blockIdx.x * 256 + threadIdx.x;  // b*(N*D) + n*D + d
    int d = idx & (Dn - 1);
    int n = (idx >> 11) & (Nn - 1);
    int b = idx >> 15;
    float h = 0.f;
    for (int c = 0; c < NCHUNK; c++) {
        size_t off = ((size_t)(b * NCHUNK + c) * Nn + n) * Dn + d;
        g_hin[off] = h;
        h = g_cA[off] * h + g_cB[off];
    }
}

// ---------------------------------------------------------------------------
// 8) Scan pass 2: replay with correct h_in, emit y
// ---------------------------------------------------------------------------
__global__ void __launch_bounds__(256) scan2_kernel(float* __restrict__ y,
                                                    const float* __restrict__ Dskip) {
    __shared__ float Bsm[LCH][Nn];
    __shared__ float Csm[LCH][Nn];
    int tid = threadIdx.x;
    int d = blockIdx.x * 256 + tid;
    int c = blockIdx.y;
    int b = blockIdx.z;
    int lbase = b * Ln + c * LCH;
#pragma unroll
    for (int i = 0; i < (LCH * Nn) / 256; i++) {
        int f = tid + i * 256; int l = f >> 4, n = f & 15;
        Bsm[l][n] = g_xdbl[(lbase + l) * En + Rn + n];
        Csm[l][n] = g_xdbl[(lbase + l) * En + Rn + Nn + n];
    }
    __syncthreads();

    float A2[Nn];
#pragma unroll
    for (int n = 0; n < Nn; n++) A2[n] = g_Aneg[d * Nn + n];
    bool unif = true;
#pragma unroll
    for (int n = 1; n < Nn; n++) unif = unif && (A2[n] == A2[0]);

    float h[Nn];
    size_t base = ((size_t)(b * NCHUNK + c) * Nn) * Dn + d;
#pragma unroll
    for (int n = 0; n < Nn; n++) h[n] = g_hin[base + (size_t)n * Dn];

    float dsk = Dskip[d];
    const float* dptr = g_delta + (size_t)lbase * Dn + d;
    const float* uptr = g_u + (size_t)lbase * Dn + d;
    float* yptr = y + (size_t)lbase * Dn + d;

    if (unif) {
        float a0 = A2[0];
#pragma unroll 4
        for (int l = 0; l < LCH; l++) {
            float dl = dptr[(size_t)l * Dn];
            float uu = uptr[(size_t)l * Dn];
            float s = dl * uu;
            float dA = __expf(dl * a0);
            float acc = 0.f;
#pragma unroll
            for (int n = 0; n < Nn; n++) {
                h[n] = dA * h[n] + s * Bsm[l][n];
                acc += h[n] * Csm[l][n];
            }
            yptr[(size_t)l * Dn] = acc + uu * dsk;
        }
    } else {
        for (int l = 0; l < LCH; l++) {
            float dl = dptr[(size_t)l * Dn];
            float uu = uptr[(size_t)l * Dn];
            float s = dl * uu;
            float acc = 0.f;
#pragma unroll
            for (int n = 0; n < Nn; n++) {
                float dA = __expf(dl * A2[n]);
                h[n] = dA * h[n] + s * Bsm[l][n];
                acc += h[n] * Csm[l][n];
            }
            yptr[(size_t)l * Dn] = acc + uu * dsk;
        }
    }
}

// ---------------------------------------------------------------------------
// Launch
// ---------------------------------------------------------------------------
extern "C" void kernel_launch(void* const* d_in, const int* in_sizes, int n_in,
                              void* d_out, int out_size) {
    const float* x     = (const float*)d_in[0];
    const float* cw    = (const float*)d_in[1];
    const float* cb    = (const float*)d_in[2];
    const float* W1    = (const float*)d_in[3];
    const float* W2    = (const float*)d_in[4];
    const float* b2    = (const float*)d_in[5];
    const float* alog  = (const float*)d_in[6];
    const float* dskip = (const float*)d_in[7];
    float* y = (float*)d_out;

    cudaFuncSetAttribute(gemm1_mma, cudaFuncAttributeMaxDynamicSharedMemorySize, G1_SMEM);
    cudaFuncSetAttribute(gemm2_mma, cudaFuncAttributeMaxDynamicSharedMemorySize, G2_SMEM);

    conv_kernel<<<(Mn * Dn) / 256, 256>>>(x, cw, cb);
    aprep_kernel<<<(Dn * Nn) / 256, 256>>>(alog);
    wconv_kernel<<<(En * Dn) / 256, 256>>>(W1, W2);
    gemm1_mma<<<dim3(Mn / 128, SPLITK), 256, G1_SMEM>>>();
    reduce1_kernel<<<(Mn * En) / 256, 256>>>();
    gemm2_mma<<<dim3(Mn / 128, Dn / 128), 256, G2_SMEM>>>(b2);
    scan1_kernel<<<dim3(Dn / 256, NCHUNK, Bn), 256>>>();
    scanmid_kernel<<<(Bn * Nn * Dn) / 256, 256>>>();
    scan2_kernel<<<dim3(Dn / 256, NCHUNK, Bn), 256>>>(y, dskip);
}

// round 8
// speedup vs baseline: 1.6324x; 1.1070x over previous
#include <cuda_runtime.h>
#include <cuda_bf16.h>
#include <math.h>
#include <stdint.h>

// ---------------------------------------------------------------------------
// Problem constants
// ---------------------------------------------------------------------------
#define Bn 2
#define Ln 1024
#define Dn 2048
#define Nn 16
#define Rn 128
#define En 160          // DT_RANK + 2*D_STATE
#define Mn (Bn*Ln)      // 2048 rows (b,l)
#define NCHUNK 16
#define LCH (Ln/NCHUNK) // 64 steps per chunk
#define SPLITK 8

// ---------------------------------------------------------------------------
// Device scratch (no allocations allowed)
// ---------------------------------------------------------------------------
__device__ __nv_bfloat16  g_uhi[(size_t)Mn*Dn];      // u split-bf16 hi
__device__ __nv_bfloat16  g_ulo[(size_t)Mn*Dn];      // u split-bf16 lo
__device__ __nv_bfloat16  g_w1hi[En*Dn];             // xproj_w hi
__device__ __nv_bfloat16  g_w1lo[En*Dn];
__device__ __nv_bfloat16  g_w2hi[Dn*Rn];             // dtproj_w hi
__device__ __nv_bfloat16  g_w2lo[Dn*Rn];
__device__ __nv_bfloat16  g_dthi[Mn*Rn];             // dt (x_dbl[:, :128]) hi
__device__ __nv_bfloat16  g_dtlo[Mn*Rn];
__device__ float          g_part[SPLITK*Mn*En];      // gemm1 split-K partials
__device__ float          g_xdbl[Mn*En];             // x_dbl = [dt | B | C]
__device__ float          g_delta[(size_t)Mn*Dn];    // softplus(...)
__device__ float          g_Aneg[Dn*Nn];             // A = -exp(A_log)
__device__ float          g_cA[Bn*NCHUNK*Nn*Dn];     // chunk prod(a)
__device__ float          g_cB[Bn*NCHUNK*Nn*Dn];     // chunk composed b
__device__ float          g_hin[Bn*NCHUNK*Nn*Dn];    // incoming h per chunk

// ---------------------------------------------------------------------------
// Warp-MMA + cp.async helpers (base sm_100 target: HMMA + LDGSTS)
// ---------------------------------------------------------------------------
__device__ __forceinline__ uint32_t smem_u32(const void* p) {
    uint32_t a;
    asm("{ .reg .u64 t; cvta.to.shared.u64 t, %1; cvt.u32.u64 %0, t; }"
        : "=r"(a) : "l"(p));
    return a;
}
__device__ __forceinline__ void cp16(uint32_t dst, const void* src) {
    asm volatile("cp.async.cg.shared.global [%0], [%1], 16;"
                 :: "r"(dst), "l"(src));
}
#define CP_COMMIT() asm volatile("cp.async.commit_group;" ::: "memory")
#define CP_WAIT0()  asm volatile("cp.async.wait_group 0;" ::: "memory")

__device__ __forceinline__ void ldsm4(uint32_t* r, uint32_t addr) {
    asm volatile("ldmatrix.sync.aligned.m8n8.x4.shared.b16 {%0,%1,%2,%3}, [%4];"
                 : "=r"(r[0]), "=r"(r[1]), "=r"(r[2]), "=r"(r[3]) : "r"(addr));
}
__device__ __forceinline__ void ldsm2(uint32_t* r, uint32_t addr) {
    asm volatile("ldmatrix.sync.aligned.m8n8.x2.shared.b16 {%0,%1}, [%2];"
                 : "=r"(r[0]), "=r"(r[1]) : "r"(addr));
}
__device__ __forceinline__ void mma_bf16(float* c, const uint32_t* a, const uint32_t* b) {
    asm volatile(
        "mma.sync.aligned.m16n8k16.row.col.f32.bf16.bf16.f32 "
        "{%0,%1,%2,%3}, {%4,%5,%6,%7}, {%8,%9}, {%0,%1,%2,%3};"
        : "+f"(c[0]), "+f"(c[1]), "+f"(c[2]), "+f"(c[3])
        : "r"(a[0]), "r"(a[1]), "r"(a[2]), "r"(a[3]), "r"(b[0]), "r"(b[1]));
}

// ---------------------------------------------------------------------------
// 1) Depthwise causal conv1d (k=4) + bias; emit split-bf16 only
// ---------------------------------------------------------------------------
__global__ void conv_kernel(const float* __restrict__ x,
                            const float* __restrict__ cw,
                            const float* __restrict__ cb) {
    int idx = blockIdx.x * 256 + threadIdx.x;   // = (b*L + l)*D + d
    int d = idx & (Dn - 1);
    int l = (idx >> 11) & (Ln - 1);
    const float* w = cw + d * 4;
    float acc = cb[d];
#pragma unroll
    for (int j = 0; j < 4; j++) {
        int ls = l - 3 + j;
        if (ls >= 0) acc += x[idx + (j - 3) * Dn] * w[j];
    }
    __nv_bfloat16 h = __float2bfloat16(acc);
    g_uhi[idx] = h;
    g_ulo[idx] = __float2bfloat16(acc - __bfloat162float(h));
}

// ---------------------------------------------------------------------------
// 2) A = -exp(A_log)
// ---------------------------------------------------------------------------
__global__ void aprep_kernel(const float* __restrict__ alog) {
    int i = blockIdx.x * 256 + threadIdx.x;
    if (i < Dn * Nn) g_Aneg[i] = -expf(alog[i]);
}

// ---------------------------------------------------------------------------
// 2b) Weight split-bf16 conversion (W1: 160x2048, W2: 2048x128)
// ---------------------------------------------------------------------------
__global__ void wconv_kernel(const float* __restrict__ W1,
                             const float* __restrict__ W2) {
    int i = blockIdx.x * 256 + threadIdx.x;
    if (i < En * Dn) {
        float v = W1[i];
        __nv_bfloat16 h = __float2bfloat16(v);
        g_w1hi[i] = h;
        g_w1lo[i] = __float2bfloat16(v - __bfloat162float(h));
    }
    if (i < Dn * Rn) {
        float v = W2[i];
        __nv_bfloat16 h = __float2bfloat16(v);
        g_w2hi[i] = h;
        g_w2lo[i] = __float2bfloat16(v - __bfloat162float(h));
    }
}

// ---------------------------------------------------------------------------
// 3) GEMM1 (mma.sync, split-bf16, 2-stage cp.async):
//    part[s][m][e] = sum_{k in split} u[m][k] * W1[e][k]
//    Block 64x160, 8 warps (2m x 4n), warp 32x40, BK=32. grid (32, 8).
//    2 CTAs/SM (70 KB smem, 40 acc regs).
// ---------------------------------------------------------------------------
#define PAD 40            // smem row stride in bf16 (80 B): conflict-free
#define G1_AHI 0
#define G1_ALO 5120
#define G1_BHI 10240
#define G1_BLO 23040
#define G1_STAGE 35840
#define G1_SMEM (2 * G1_STAGE)

__global__ void __launch_bounds__(256, 2) gemm1_mma() {
    extern __shared__ char smem[];
    uint32_t sb = smem_u32(smem);
    int tid = threadIdx.x;
    int lane = tid & 31, wid = tid >> 5;
    int wm = wid & 1, wn = wid >> 1;       // 2 x 4 warps
    int m0 = blockIdx.x * 64;
    int kbase = blockIdx.y * (Dn / SPLITK);

    float acc[2][5][4];
#pragma unroll
    for (int i = 0; i < 2; i++)
#pragma unroll
        for (int j = 0; j < 5; j++)
#pragma unroll
            for (int t = 0; t < 4; t++) acc[i][j][t] = 0.f;

    int a_r = (lane & 7) + ((lane >> 3) & 1) * 8;
    int a_c = (lane >> 4) * 8;
    int b_r4 = (lane & 7) + (lane >> 4) * 8;
    int b_c  = ((lane >> 3) & 1) * 8;
    int b_r2 = lane & 7;

    auto load_stage = [&](int st, int kcol) {
        uint32_t sbase = sb + st * G1_STAGE;
        {                                             // A: 256 chunks
            int row = tid >> 2, c16 = tid & 3;
            uint32_t so = sbase + row * 80 + c16 * 16;
            size_t g = (size_t)(m0 + row) * Dn + kcol + c16 * 8;
            cp16(so + G1_AHI, g_uhi + g);
            cp16(so + G1_ALO, g_ulo + g);
        }
#pragma unroll
        for (int i = 0; i < 3; i++) {                 // B: 640 chunks
            int cidx = tid + i * 256;
            if (cidx < 640) {
                int row = cidx >> 2, c16 = cidx & 3;
                uint32_t so = sbase + row * 80 + c16 * 16;
                size_t g = (size_t)row * Dn + kcol + c16 * 8;
                cp16(so + G1_BHI, g_w1hi + g);
                cp16(so + G1_BLO, g_w1lo + g);
            }
        }
        CP_COMMIT();
    };

    load_stage(0, kbase);
    for (int kb = 0; kb < 8; kb++) {
        CP_WAIT0();
        __syncthreads();
        if (kb + 1 < 8) load_stage((kb + 1) & 1, kbase + (kb + 1) * 32);

        uint32_t sbase = sb + (kb & 1) * G1_STAGE;
#pragma unroll
        for (int kk = 0; kk < 32; kk += 16) {
            uint32_t ah[2][4], al[2][4], bh[5][2], bl[5][2];
#pragma unroll
            for (int mt = 0; mt < 2; mt++) {
                uint32_t a = sbase + G1_AHI +
                    (uint32_t)(((wm * 32 + mt * 16 + a_r) * PAD + kk + a_c) * 2);
                ldsm4(ah[mt], a);
                ldsm4(al[mt], a + (G1_ALO - G1_AHI));
            }
#pragma unroll
            for (int g = 0; g < 2; g++) {
                uint32_t a = sbase + G1_BHI +
                    (uint32_t)(((wn * 40 + g * 16 + b_r4) * PAD + kk + b_c) * 2);
                uint32_t t[4];
                ldsm4(t, a);
                bh[2 * g][0] = t[0]; bh[2 * g][1] = t[1];
                bh[2 * g + 1][0] = t[2]; bh[2 * g + 1][1] = t[3];
                ldsm4(t, a + (G1_BLO - G1_BHI));
                bl[2 * g][0] = t[0]; bl[2 * g][1] = t[1];
                bl[2 * g + 1][0] = t[2]; bl[2 * g + 1][1] = t[3];
            }
            {
                uint32_t a = sbase + G1_BHI +
                    (uint32_t)(((wn * 40 + 32 + b_r2) * PAD + kk + b_c) * 2);
                ldsm2(bh[4], a);
                ldsm2(bl[4], a + (G1_BLO - G1_BHI));
            }
#pragma unroll
            for (int mt = 0; mt < 2; mt++)
#pragma unroll
                for (int nt = 0; nt < 5; nt++) {
                    mma_bf16(acc[mt][nt], ah[mt], bh[nt]);
                    mma_bf16(acc[mt][nt], ah[mt], bl[nt]);
                    mma_bf16(acc[mt][nt], al[mt], bh[nt]);
                }
        }
    }

    // Epilogue -> split-K partials
    float* outp = g_part + (size_t)blockIdx.y * (Mn * En);
#pragma unroll
    for (int mt = 0; mt < 2; mt++) {
        int row = m0 + wm * 32 + mt * 16 + (lane >> 2);
#pragma unroll
        for (int nt = 0; nt < 5; nt++) {
            int col = wn * 40 + nt * 8 + (lane & 3) * 2;
            *(float2*)(outp + (size_t)row * En + col) =
                make_float2(acc[mt][nt][0], acc[mt][nt][1]);
            *(float2*)(outp + (size_t)(row + 8) * En + col) =
                make_float2(acc[mt][nt][2], acc[mt][nt][3]);
        }
    }
}

// ---------------------------------------------------------------------------
// 4) Reduce split-K partials -> x_dbl (float4); emit dt split-bf16 for e<128
// ---------------------------------------------------------------------------
__global__ void reduce1_kernel() {
    int i4 = blockIdx.x * 256 + threadIdx.x;  // < Mn*En/4
    int i = i4 * 4;
    float4 s = make_float4(0.f, 0.f, 0.f, 0.f);
#pragma unroll
    for (int p = 0; p < SPLITK; p++) {
        float4 v = *(const float4*)(g_part + (size_t)p * (Mn * En) + i);
        s.x += v.x; s.y += v.y; s.z += v.z; s.w += v.w;
    }
    *(float4*)(g_xdbl + i) = s;
    int m = i / En;
    int e = i - m * En;
    if (e < Rn) {
        float vv[4] = {s.x, s.y, s.z, s.w};
        __nv_bfloat16 hi4[4], lo4[4];
#pragma unroll
        for (int t = 0; t < 4; t++) {
            hi4[t] = __float2bfloat16(vv[t]);
            lo4[t] = __float2bfloat16(vv[t] - __bfloat162float(hi4[t]));
        }
        *(uint2*)(g_dthi + m * Rn + e) = *(uint2*)hi4;
        *(uint2*)(g_dtlo + m * Rn + e) = *(uint2*)lo4;
    }
}

// ---------------------------------------------------------------------------
// 5) GEMM2 (mma.sync, split-bf16, 2-stage cp.async) + bias + softplus:
//    delta[m][d] = softplus(sum_r dt[m][r]*W2[d][r] + b2[d])
//    Block 64x128, 8 warps (2m x 4n), warp 32x32, BK=32. grid (32, 16).
// ---------------------------------------------------------------------------
#define G2_AHI 0
#define G2_ALO 5120
#define G2_BHI 10240
#define G2_BLO 20480
#define G2_STAGE 30720
#define G2_SMEM (2 * G2_STAGE)

__global__ void __launch_bounds__(256, 2) gemm2_mma(const float* __restrict__ b2) {
    extern __shared__ char smem[];
    uint32_t sb = smem_u32(smem);
    int tid = threadIdx.x;
    int lane = tid & 31, wid = tid >> 5;
    int wm = wid & 1, wn = wid >> 1;       // 2 x 4 warps
    int m0 = blockIdx.x * 64, n0 = blockIdx.y * 128;

    float acc[2][4][4];
#pragma unroll
    for (int i = 0; i < 2; i++)
#pragma unroll
        for (int j = 0; j < 4; j++)
#pragma unroll
            for (int t = 0; t < 4; t++) acc[i][j][t] = 0.f;

    int a_r = (lane & 7) + ((lane >> 3) & 1) * 8;
    int a_c = (lane >> 4) * 8;
    int b_r4 = (lane & 7) + (lane >> 4) * 8;
    int b_c  = ((lane >> 3) & 1) * 8;

    auto load_stage = [&](int st, int kcol) {
        uint32_t sbase = sb + st * G2_STAGE;
        {                                             // A: 256 chunks
            int row = tid >> 2, c16 = tid & 3;
            uint32_t so = sbase + row * 80 + c16 * 16;
            size_t g = (size_t)(m0 + row) * Rn + kcol + c16 * 8;
            cp16(so + G2_AHI, g_dthi + g);
            cp16(so + G2_ALO, g_dtlo + g);
        }
#pragma unroll
        for (int i = 0; i < 2; i++) {                 // B: 512 chunks
            int cidx = tid + i * 256;
            int row = cidx >> 2, c16 = cidx & 3;
            uint32_t so = sbase + row * 80 + c16 * 16;
            size_t g = (size_t)(n0 + row) * Rn + kcol + c16 * 8;
            cp16(so + G2_BHI, g_w2hi + g);
            cp16(so + G2_BLO, g_w2lo + g);
        }
        CP_COMMIT();
    };

    load_stage(0, 0);
    for (int kb = 0; kb < 4; kb++) {
        CP_WAIT0();
        __syncthreads();
        if (kb + 1 < 4) load_stage((kb + 1) & 1, (kb + 1) * 32);

        uint32_t sbase = sb + (kb & 1) * G2_STAGE;
#pragma unroll
        for (int kk = 0; kk < 32; kk += 16) {
            uint32_t ah[2][4], al[2][4], bh[4][2], bl[4][2];
#pragma unroll
            for (int mt = 0; mt < 2; mt++) {
                uint32_t a = sbase + G2_AHI +
                    (uint32_t)(((wm * 32 + mt * 16 + a_r) * PAD + kk + a_c) * 2);
                ldsm4(ah[mt], a);
                ldsm4(al[mt], a + (G2_ALO - G2_AHI));
            }
#pragma unroll
            for (int g = 0; g < 2; g++) {
                uint32_t a = sbase + G2_BHI +
                    (uint32_t)(((wn * 32 + g * 16 + b_r4) * PAD + kk + b_c) * 2);
                uint32_t t[4];
                ldsm4(t, a);
                bh[2 * g][0] = t[0]; bh[2 * g][1] = t[1];
                bh[2 * g + 1][0] = t[2]; bh[2 * g + 1][1] = t[3];
                ldsm4(t, a + (G2_BLO - G2_BHI));
                bl[2 * g][0] = t[0]; bl[2 * g][1] = t[1];
                bl[2 * g + 1][0] = t[2]; bl[2 * g + 1][1] = t[3];
            }
#pragma unroll
            for (int mt = 0; mt < 2; mt++)
#pragma unroll
                for (int nt = 0; nt < 4; nt++) {
                    mma_bf16(acc[mt][nt], ah[mt], bh[nt]);
                    mma_bf16(acc[mt][nt], ah[mt], bl[nt]);
                    mma_bf16(acc[mt][nt], al[mt], bh[nt]);
                }
        }
    }

    // Epilogue: bias + softplus straight from registers
#pragma unroll
    for (int mt = 0; mt < 2; mt++) {
        int row = m0 + wm * 32 + mt * 16 + (lane >> 2);
#pragma unroll
        for (int nt = 0; nt < 4; nt++) {
            int col = n0 + wn * 32 + nt * 8 + (lane & 3) * 2;
            float bb0 = __ldg(b2 + col), bb1 = __ldg(b2 + col + 1);
            float t0 = acc[mt][nt][0] + bb0, t1 = acc[mt][nt][1] + bb1;
            float t2 = acc[mt][nt][2] + bb0, t3 = acc[mt][nt][3] + bb1;
            t0 = (t0 > 20.f) ? t0 : log1pf(__expf(t0));
            t1 = (t1 > 20.f) ? t1 : log1pf(__expf(t1));
            t2 = (t2 > 20.f) ? t2 : log1pf(__expf(t2));
            t3 = (t3 > 20.f) ? t3 : log1pf(__expf(t3));
            *(float2*)(g_delta + (size_t)row * Dn + col) = make_float2(t0, t1);
            *(float2*)(g_delta + (size_t)(row + 8) * Dn + col) = make_float2(t2, t3);
        }
    }
}

// ---------------------------------------------------------------------------
// 6) Scan pass 1: per (b,d,chunk) compute (prod a, composed b) over 64 steps
// ---------------------------------------------------------------------------
__global__ void __launch_bounds__(256) scan1_kernel() {
    __shared__ float Bsm[LCH][Nn];
    int tid = threadIdx.x;
    int d = blockIdx.x * 256 + tid;
    int c = blockIdx.y;
    int b = blockIdx.z;
    int lbase = b * Ln + c * LCH;
#pragma unroll
    for (int i = 0; i < (LCH * Nn) / 256; i++) {
        int f = tid + i * 256; int l = f >> 4, n = f & 15;
        Bsm[l][n] = g_xdbl[(lbase + l) * En + Rn + n];
    }
    __syncthreads();

    float A2[Nn];
#pragma unroll
    for (int n = 0; n < Nn; n++) A2[n] = g_Aneg[d * Nn + n];
    bool unif = true;
#pragma unroll
    for (int n = 1; n < Nn; n++) unif = unif && (A2[n] == A2[0]);

    float Ap[Nn], Bs[Nn];
#pragma unroll
    for (int n = 0; n < Nn; n++) { Ap[n] = 1.f; Bs[n] = 0.f; }

    const float* dptr = g_delta + (size_t)lbase * Dn + d;
    const __nv_bfloat16* uh = g_uhi + (size_t)lbase * Dn + d;
    const __nv_bfloat16* ul = g_ulo + (size_t)lbase * Dn + d;

    if (unif) {
        float a0 = A2[0];
        float ap = 1.f;
#pragma unroll 4
        for (int l = 0; l < LCH; l++) {
            float dl = dptr[(size_t)l * Dn];
            float uu = __bfloat162float(uh[(size_t)l * Dn]) +
                       __bfloat162float(ul[(size_t)l * Dn]);
            float s = dl * uu;
            float dA = __expf(dl * a0);
            ap *= dA;
#pragma unroll
            for (int n = 0; n < Nn; n++) Bs[n] = dA * Bs[n] + s * Bsm[l][n];
        }
#pragma unroll
        for (int n = 0; n < Nn; n++) Ap[n] = ap;
    } else {
        for (int l = 0; l < LCH; l++) {
            float dl = dptr[(size_t)l * Dn];
            float uu = __bfloat162float(uh[(size_t)l * Dn]) +
                       __bfloat162float(ul[(size_t)l * Dn]);
            float s = dl * uu;
#pragma unroll
            for (int n = 0; n < Nn; n++) {
                float dA = __expf(dl * A2[n]);
                Ap[n] *= dA;
                Bs[n] = dA * Bs[n] + s * Bsm[l][n];
            }
        }
    }
    size_t base = ((size_t)(b * NCHUNK + c) * Nn) * Dn + d;
#pragma unroll
    for (int n = 0; n < Nn; n++) {
        g_cA[base + (size_t)n * Dn] = Ap[n];
        g_cB[base + (size_t)n * Dn] = Bs[n];
    }
}

// ---------------------------------------------------------------------------
// 7) Inter-chunk scan: per (b,d,n) propagate h across 16 chunks
// ---------------------------------------------------------------------------
__global__ void scanmid_kernel() {
    int idx = blockIdx.x * 256 + threadIdx.x;  // b*(N*D) + n*D + d
    int d = idx & (Dn - 1);
    int n = (idx >> 11) & (Nn - 1);
    int b = idx >> 15;
    float h = 0.f;
    for (int c = 0; c < NCHUNK; c++) {
        size_t off = ((size_t)(b * NCHUNK + c) * Nn + n) * Dn + d;
        g_hin[off] = h;
        h = g_cA[off] * h + g_cB[off];
    }
}

// ---------------------------------------------------------------------------
// 8) Scan pass 2: replay with correct h_in, emit y
// ---------------------------------------------------------------------------
__global__ void __launch_bounds__(256) scan2_kernel(float* __restrict__ y,
                                                    const float* __restrict__ Dskip) {
    __shared__ float Bsm[LCH][Nn];
    __shared__ float Csm[LCH][Nn];
    int tid = threadIdx.x;
    int d = blockIdx.x * 256 + tid;
    int c = blockIdx.y;
    int b = blockIdx.z;
    int lbase = b * Ln + c * LCH;
#pragma unroll
    for (int i = 0; i < (LCH * Nn) / 256; i++) {
        int f = tid + i * 256; int l = f >> 4, n = f & 15;
        Bsm[l][n] = g_xdbl[(lbase + l) * En + Rn + n];
        Csm[l][n] = g_xdbl[(lbase + l) * En + Rn + Nn + n];
    }
    __syncthreads();

    float A2[Nn];
#pragma unroll
    for (int n = 0; n < Nn; n++) A2[n] = g_Aneg[d * Nn + n];
    bool unif = true;
#pragma unroll
    for (int n = 1; n < Nn; n++) unif = unif && (A2[n] == A2[0]);

    float h[Nn];
    size_t base = ((size_t)(b * NCHUNK + c) * Nn) * Dn + d;
#pragma unroll
    for (int n = 0; n < Nn; n++) h[n] = g_hin[base + (size_t)n * Dn];

    float dsk = Dskip[d];
    const float* dptr = g_delta + (size_t)lbase * Dn + d;
    const __nv_bfloat16* uh = g_uhi + (size_t)lbase * Dn + d;
    const __nv_bfloat16* ul = g_ulo + (size_t)lbase * Dn + d;
    float* yptr = y + (size_t)lbase * Dn + d;

    if (unif) {
        float a0 = A2[0];
#pragma unroll 4
        for (int l = 0; l < LCH; l++) {
            float dl = dptr[(size_t)l * Dn];
            float uu = __bfloat162float(uh[(size_t)l * Dn]) +
                       __bfloat162float(ul[(size_t)l * Dn]);
            float s = dl * uu;
            float dA = __expf(dl * a0);
            float acc = 0.f;
#pragma unroll
            for (int n = 0; n < Nn; n++) {
                h[n] = dA * h[n] + s * Bsm[l][n];
                acc += h[n] * Csm[l][n];
            }
            yptr[(size_t)l * Dn] = acc + uu * dsk;
        }
    } else {
        for (int l = 0; l < LCH; l++) {
            float dl = dptr[(size_t)l * Dn];
            float uu = __bfloat162float(uh[(size_t)l * Dn]) +
                       __bfloat162float(ul[(size_t)l * Dn]);
            float s = dl * uu;
            float acc = 0.f;
#pragma unroll
            for (int n = 0; n < Nn; n++) {
                float dA = __expf(dl * A2[n]);
                h[n] = dA * h[n] + s * Bsm[l][n];
                acc += h[n] * Csm[l][n];
            }
            yptr[(size_t)l * Dn] = acc + uu * dsk;
        }
    }
}

// ---------------------------------------------------------------------------
// Launch
// ---------------------------------------------------------------------------
extern "C" void kernel_launch(void* const* d_in, const int* in_sizes, int n_in,
                              void* d_out, int out_size) {
    const float* x     = (const float*)d_in[0];
    const float* cw    = (const float*)d_in[1];
    const float* cb    = (const float*)d_in[2];
    const float* W1    = (const float*)d_in[3];
    const float* W2    = (const float*)d_in[4];
    const float* b2    = (const float*)d_in[5];
    const float* alog  = (const float*)d_in[6];
    const float* dskip = (const float*)d_in[7];
    float* y = (float*)d_out;

    cudaFuncSetAttribute(gemm1_mma, cudaFuncAttributeMaxDynamicSharedMemorySize, G1_SMEM);
    cudaFuncSetAttribute(gemm2_mma, cudaFuncAttributeMaxDynamicSharedMemorySize, G2_SMEM);

    conv_kernel<<<(Mn * Dn) / 256, 256>>>(x, cw, cb);
    aprep_kernel<<<(Dn * Nn) / 256, 256>>>(alog);
    wconv_kernel<<<(En * Dn) / 256, 256>>>(W1, W2);
    gemm1_mma<<<dim3(Mn / 64, SPLITK), 256, G1_SMEM>>>();
    reduce1_kernel<<<(Mn * En / 4) / 256, 256>>>();
    gemm2_mma<<<dim3(Mn / 64, Dn / 128), 256, G2_SMEM>>>(b2);
    scan1_kernel<<<dim3(Dn / 256, NCHUNK, Bn), 256>>>();
    scanmid_kernel<<<(Bn * Nn * Dn) / 256, 256>>>();
    scan2_kernel<<<dim3(Dn / 256, NCHUNK, Bn), 256>>>(y, dskip);
}